// round 4
// baseline (speedup 1.0000x reference)
#include <cuda_runtime.h>
#include <cuda_bf16.h>
#include <cstdint>

typedef __nv_bfloat16 bf;

#define NB 16
#define SS_ 1024
#define DD_ 1024
#define MTOT (NB*SS_)              // 16384
#define PLANE (MTOT*DD_)           // 16,777,216
#define BATSTR (SS_*DD_)           // 1,048,576

// ---------------- device scratch (statics; no allocation allowed) ----------
__device__ bf g_xh[6][PLANE];      __device__ bf g_xl[6][PLANE];      // split inputs
__device__ bf g_wh[6][DD_*DD_];    __device__ bf g_wl[6][DD_*DD_];    // split weights
__device__ bf g_ph[6][PLANE];      __device__ bf g_pl[6][PLANE];      // proj outputs
__device__ bf g_th[3][PLANE];      __device__ bf g_tl[3][PLANE];      // transposed kr,vr,vi
__device__ bf g_ah[PLANE];         __device__ bf g_al[PLANE];         // split attn
__device__ float g_att[PLANE];     // raw scores
__device__ float g_or[PLANE];      __device__ float g_oi[PLANE];

// ---------------- helpers ---------------------------------------------------
__device__ __forceinline__ uint32_t smem_u32(const void* p) {
    uint32_t a;
    asm("{ .reg .u64 t; cvta.to.shared.u64 t, %1; cvt.u32.u64 %0, t; }"
        : "=r"(a) : "l"(p));
    return a;
}
__device__ __forceinline__ void cp16(uint32_t s, const void* g) {
    asm volatile("cp.async.cg.shared.global [%0], [%1], 16;" :: "r"(s), "l"(g));
}
#define CP_COMMIT() asm volatile("cp.async.commit_group;" ::: "memory")
#define CP_WAIT1()  asm volatile("cp.async.wait_group 1;" ::: "memory")
#define CP_WAIT0()  asm volatile("cp.async.wait_group 0;" ::: "memory")

__device__ __forceinline__ void ldm4(uint32_t* r, uint32_t addr) {
    asm volatile("ldmatrix.sync.aligned.m8n8.x4.shared.b16 {%0,%1,%2,%3}, [%4];"
        : "=r"(r[0]), "=r"(r[1]), "=r"(r[2]), "=r"(r[3]) : "r"(addr));
}
__device__ __forceinline__ void mma16816(float* d, const uint32_t* a, const uint32_t* b) {
    asm volatile(
        "mma.sync.aligned.m16n8k16.row.col.f32.bf16.bf16.f32 "
        "{%0,%1,%2,%3}, {%4,%5,%6,%7}, {%8,%9}, {%0,%1,%2,%3};"
        : "+f"(d[0]), "+f"(d[1]), "+f"(d[2]), "+f"(d[3])
        : "r"(a[0]), "r"(a[1]), "r"(a[2]), "r"(a[3]), "r"(b[0]), "r"(b[1]));
}

// ---------------- tensor-core split-bf16 NT GEMM ----------------------------
// C[m,n] = sum_pair sum_k A[m,k]*B[n,k], fp32 acc, 3-part bf16 split:
//   hi*hi + hi*lo + lo*hi  (error ~2^-16)
// BM=128, BN=256, BK=32; 8 warps, warp tile 64x64.
#define BM 128
#define BN 256
#define STAGES 3
#define PITCHB 80                       // 32 bf16 + 8 pad
#define A_PART (128*PITCHB)             // 10240
#define B_PART (256*PITCHB)             // 20480
#define OFF_AL A_PART                   // 10240
#define OFF_BH (2*A_PART)               // 20480
#define OFF_BL (2*A_PART + B_PART)      // 40960
#define STG_BYTES (2*A_PART + 2*B_PART) // 61440
#define DSM_BYTES (STAGES*STG_BYTES)    // 184320

// EPI: 0 = write fp32 C ; 1 = add bias, write split bf16 hi/lo
template<int EPI>
__global__ __launch_bounds__(256, 1) void gemm_k(int job, const float* __restrict__ bias) {
    const bf *Ah[2], *Al[2], *Bh[2], *Bl[2];
    size_t bstr = 0; int npair = 1;
    float* Cf = nullptr; bf* Ch = nullptr; bf* Cl = nullptr;
    if (job < 6) {            // projections: X @ W^T + b -> split bf16
        Ah[0] = g_xh[job]; Al[0] = g_xl[job];
        Bh[0] = g_wh[job]; Bl[0] = g_wl[job];
        Ch = g_ph[job]; Cl = g_pl[job];
        Ah[1] = Ah[0]; Al[1] = Al[0]; Bh[1] = Bh[0]; Bl[1] = Bl[0];
    } else if (job == 6) {    // scores: qr@krT + qi@ki^T
        Ah[0] = g_ph[0]; Al[0] = g_pl[0]; Bh[0] = g_th[0]; Bl[0] = g_tl[0];
        Ah[1] = g_ph[1]; Al[1] = g_pl[1]; Bh[1] = g_ph[3]; Bl[1] = g_pl[3];
        npair = 2; bstr = BATSTR; Cf = g_att;
    } else {                  // av: attn @ v
        int w = job - 7;
        Ah[0] = g_ah; Al[0] = g_al;
        Bh[0] = g_th[1 + w]; Bl[0] = g_tl[1 + w];
        bstr = BATSTR; Cf = w ? g_oi : g_or;
        Ah[1] = Ah[0]; Al[1] = Al[0]; Bh[1] = Bh[0]; Bl[1] = Bl[0];
    }
    const size_t zoff  = (size_t)blockIdx.z * bstr;
    const size_t zoffb = zoff * 2;
    const int m0 = blockIdx.y * BM, n0 = blockIdx.x * BN;
    const int T = npair * 32;

    extern __shared__ char dsm[];
    const uint32_t base = smem_u32(dsm);
    const int tid = threadIdx.x, wid = tid >> 5, lane = tid & 31;
    const int wm = (wid >> 2) * 64;       // 2 warp rows
    const int wn = (wid & 3) * 64;        // 4 warp cols of 64

    // loader mapping
    const int a_ldrow = tid >> 1;                // 0..127
    const uint32_t a_ldoff = (tid & 1) * 32;     // byte half of 64B row

    auto loads = [&](int it, int s) {
        const int pr = it >> 5;
        const int kt = it & 31;
        const uint32_t sb = base + s * STG_BYTES;
        // A: thread -> row (tid>>1), 32B half
        {
            const size_t ga = zoffb + ((size_t)(m0 + a_ldrow) * 1024 + kt * 32) * 2 + a_ldoff;
            const uint32_t so = a_ldrow * PITCHB + a_ldoff;
            const char* pAh = (const char*)Ah[pr] + ga;
            const char* pAl = (const char*)Al[pr] + ga;
            cp16(sb + so,              pAh);
            cp16(sb + so + 16,         pAh + 16);
            cp16(sb + OFF_AL + so,     pAl);
            cp16(sb + OFF_AL + so + 16, pAl + 16);
        }
        // B: thread -> row tid, full 64B row
        {
            const size_t gb = zoffb + ((size_t)(n0 + tid) * 1024 + kt * 32) * 2;
            const uint32_t so = tid * PITCHB;
            const char* pBh = (const char*)Bh[pr] + gb;
            const char* pBl = (const char*)Bl[pr] + gb;
            #pragma unroll
            for (int c = 0; c < 4; c++) {
                cp16(sb + OFF_BH + so + c * 16, pBh + c * 16);
                cp16(sb + OFF_BL + so + c * 16, pBl + c * 16);
            }
        }
    };

    // ldmatrix per-lane address components
    const int g = lane >> 3, lr = lane & 7;
    const uint32_t a_row = ((g & 1) * 8 + lr) * PITCHB;
    const uint32_t a_col = (g >> 1) * 16;
    const uint32_t b_row = ((g >> 1) * 8 + lr) * PITCHB;
    const uint32_t b_col = (g & 1) * 16;

    float acc[4][8][4] = {};

    loads(0, 0); CP_COMMIT();
    loads(1, 1); CP_COMMIT();

    for (int it = 0; it < T; ++it) {
        CP_WAIT1();
        __syncthreads();

        const uint32_t sb = base + (it % STAGES) * STG_BYTES;
        #pragma unroll
        for (int ks = 0; ks < 2; ++ks) {
            uint32_t ah[4][4], al[4][4], bh4[4][4], bl4[4][4];
            const uint32_t ak = ks * 32 + a_col;
            const uint32_t bk = ks * 32 + b_col;
            #pragma unroll
            for (int mf = 0; mf < 4; ++mf) {
                const uint32_t ro = (uint32_t)(wm + mf * 16) * PITCHB + a_row + ak;
                ldm4(ah[mf], sb + ro);
                ldm4(al[mf], sb + OFF_AL + ro);
            }
            #pragma unroll
            for (int nf2 = 0; nf2 < 4; ++nf2) {
                const uint32_t ro = (uint32_t)(wn + nf2 * 16) * PITCHB + b_row + bk;
                ldm4(bh4[nf2], sb + OFF_BH + ro);
                ldm4(bl4[nf2], sb + OFF_BL + ro);
            }
            #pragma unroll
            for (int mi = 0; mi < 4; ++mi)
                #pragma unroll
                for (int ni = 0; ni < 8; ++ni) {
                    const uint32_t* bh_f = &bh4[ni >> 1][(ni & 1) * 2];
                    const uint32_t* bl_f = &bl4[ni >> 1][(ni & 1) * 2];
                    mma16816(acc[mi][ni], ah[mi], bh_f);   // hi*hi
                    mma16816(acc[mi][ni], ah[mi], bl_f);   // hi*lo
                    mma16816(acc[mi][ni], al[mi], bh_f);   // lo*hi
                }
        }
        __syncthreads();
        if (it + 2 < T) loads(it + 2, (it + 2) % STAGES);
        CP_COMMIT();
    }
    CP_WAIT0();

    // ---------------- epilogue (register -> gmem) ----------------
    const int em = m0 + wm + (lane >> 2);
    const int en = n0 + wn + (lane & 3) * 2;
    #pragma unroll
    for (int mi = 0; mi < 4; ++mi) {
        #pragma unroll
        for (int ni = 0; ni < 8; ++ni) {
            const int m = em + mi * 16;
            const int n = en + ni * 8;
            const float* a = acc[mi][ni];
            if (EPI == 0) {
                float2 v0 = {a[0], a[1]};
                float2 v1 = {a[2], a[3]};
                *(float2*)&Cf[zoff + (size_t)m * 1024 + n]       = v0;
                *(float2*)&Cf[zoff + (size_t)(m + 8) * 1024 + n] = v1;
            } else {
                const float b0 = __ldg(&bias[n]), b1 = __ldg(&bias[n + 1]);
                #pragma unroll
                for (int rr = 0; rr < 2; ++rr) {
                    const float v0 = a[rr * 2 + 0] + b0;
                    const float v1 = a[rr * 2 + 1] + b1;
                    bf h0 = __float2bfloat16_rn(v0), h1 = __float2bfloat16_rn(v1);
                    bf l0 = __float2bfloat16_rn(v0 - __bfloat162float(h0));
                    bf l1 = __float2bfloat16_rn(v1 - __bfloat162float(h1));
                    const size_t off = (size_t)(m + rr * 8) * 1024 + n;
                    __nv_bfloat162 t;
                    t.x = h0; t.y = h1; *(__nv_bfloat162*)(Ch + off) = t;
                    t.x = l0; t.y = l1; *(__nv_bfloat162*)(Cl + off) = t;
                }
            }
        }
    }
}

// ---------------- fp32 -> (hi, lo) bf16 split -------------------------------
__global__ __launch_bounds__(256) void split_k(int job, const float4* __restrict__ src) {
    bf *h, *l; int n4;
    if (job < 6) { h = g_xh[job]; l = g_xl[job]; n4 = PLANE / 4; }
    else         { h = g_wh[job - 6]; l = g_wl[job - 6]; n4 = (DD_ * DD_) / 4; }
    const int i = blockIdx.x * 256 + threadIdx.x;
    if (i >= n4) return;
    const float4 v = src[i];
    bf h0 = __float2bfloat16_rn(v.x), h1 = __float2bfloat16_rn(v.y);
    bf h2 = __float2bfloat16_rn(v.z), h3 = __float2bfloat16_rn(v.w);
    bf l0 = __float2bfloat16_rn(v.x - __bfloat162float(h0));
    bf l1 = __float2bfloat16_rn(v.y - __bfloat162float(h1));
    bf l2 = __float2bfloat16_rn(v.z - __bfloat162float(h2));
    bf l3 = __float2bfloat16_rn(v.w - __bfloat162float(h3));
    __nv_bfloat162 t;
    t.x = h0; t.y = h1; *(__nv_bfloat162*)(h + 4 * (size_t)i)     = t;
    t.x = h2; t.y = h3; *(__nv_bfloat162*)(h + 4 * (size_t)i + 2) = t;
    t.x = l0; t.y = l1; *(__nv_bfloat162*)(l + 4 * (size_t)i)     = t;
    t.x = l2; t.y = l3; *(__nv_bfloat162*)(l + 4 * (size_t)i + 2) = t;
}

// ---------------- batched 1024x1024 bf16 transpose (kr, vr, vi hi+lo) -------
__global__ __launch_bounds__(256) void transpose_k() {
    const int z = blockIdx.z, t = z >> 4, b = z & 15;
    const int si = (t == 0) ? 2 : (t == 1 ? 4 : 5);
    const bf* sh = g_ph[si] + (size_t)b * BATSTR;
    const bf* sl = g_pl[si] + (size_t)b * BATSTR;
    bf* dh = g_th[t] + (size_t)b * BATSTR;
    bf* dl = g_tl[t] + (size_t)b * BATSTR;
    __shared__ bf Th[32][33], Tl[32][33];
    const int tx = threadIdx.x, ty = threadIdx.y;
    const int x0 = blockIdx.x * 32, y0 = blockIdx.y * 32;
    #pragma unroll
    for (int j = ty; j < 32; j += 8) {
        Th[j][tx] = sh[(size_t)(y0 + j) * 1024 + x0 + tx];
        Tl[j][tx] = sl[(size_t)(y0 + j) * 1024 + x0 + tx];
    }
    __syncthreads();
    #pragma unroll
    for (int j = ty; j < 32; j += 8) {
        dh[(size_t)(x0 + j) * 1024 + y0 + tx] = Th[tx][j];
        dl[(size_t)(x0 + j) * 1024 + y0 + tx] = Tl[tx][j];
    }
}

// ---------------- softmax (scale 0.125 folded) -> split bf16 -----------------
__global__ __launch_bounds__(256) void softmax_k() {
    __shared__ float red[8];
    const size_t rowo = (size_t)blockIdx.x * 1024;
    const float* p = g_att + rowo;
    const int tid = threadIdx.x;

    float4 v = ((const float4*)p)[tid];
    v.x *= 0.125f; v.y *= 0.125f; v.z *= 0.125f; v.w *= 0.125f;

    float m = fmaxf(fmaxf(v.x, v.y), fmaxf(v.z, v.w));
    #pragma unroll
    for (int o = 16; o; o >>= 1) m = fmaxf(m, __shfl_xor_sync(0xffffffffu, m, o));
    if ((tid & 31) == 0) red[tid >> 5] = m;
    __syncthreads();
    float M = red[0];
    #pragma unroll
    for (int i = 1; i < 8; i++) M = fmaxf(M, red[i]);
    __syncthreads();

    v.x = expf(v.x - M); v.y = expf(v.y - M);
    v.z = expf(v.z - M); v.w = expf(v.w - M);
    float s = v.x + v.y + v.z + v.w;
    #pragma unroll
    for (int o = 16; o; o >>= 1) s += __shfl_xor_sync(0xffffffffu, s, o);
    if ((tid & 31) == 0) red[tid >> 5] = s;
    __syncthreads();
    float Tt = 0.f;
    #pragma unroll
    for (int i = 0; i < 8; i++) Tt += red[i];
    const float inv = 1.0f / Tt;
    v.x *= inv; v.y *= inv; v.z *= inv; v.w *= inv;

    bf h0 = __float2bfloat16_rn(v.x), h1 = __float2bfloat16_rn(v.y);
    bf h2 = __float2bfloat16_rn(v.z), h3 = __float2bfloat16_rn(v.w);
    bf l0 = __float2bfloat16_rn(v.x - __bfloat162float(h0));
    bf l1 = __float2bfloat16_rn(v.y - __bfloat162float(h1));
    bf l2 = __float2bfloat16_rn(v.z - __bfloat162float(h2));
    bf l3 = __float2bfloat16_rn(v.w - __bfloat162float(h3));
    const size_t o4 = rowo + (size_t)tid * 4;
    __nv_bfloat162 t;
    t.x = h0; t.y = h1; *(__nv_bfloat162*)(g_ah + o4)     = t;
    t.x = h2; t.y = h3; *(__nv_bfloat162*)(g_ah + o4 + 2) = t;
    t.x = l0; t.y = l1; *(__nv_bfloat162*)(g_al + o4)     = t;
    t.x = l2; t.y = l3; *(__nv_bfloat162*)(g_al + o4 + 2) = t;
}

// ---------------- complex LayerNorm + writeback ------------------------------
__global__ __launch_bounds__(256) void lnorm_k(const float* __restrict__ a2,
                                               const float* __restrict__ b2,
                                               float* __restrict__ out) {
    __shared__ float red[5][8];
    const size_t row = blockIdx.x;
    const int tid = threadIdx.x;
    const float4 ar = ((const float4*)(g_or + row * 1024))[tid];
    const float4 ai = ((const float4*)(g_oi + row * 1024))[tid];

    float sr  = ar.x + ar.y + ar.z + ar.w;
    float si  = ai.x + ai.y + ai.z + ai.w;
    float srr = ar.x*ar.x + ar.y*ar.y + ar.z*ar.z + ar.w*ar.w;
    float sii = ai.x*ai.x + ai.y*ai.y + ai.z*ai.z + ai.w*ai.w;
    float sri = ar.x*ai.x + ar.y*ai.y + ar.z*ai.z + ar.w*ai.w;
    #pragma unroll
    for (int o = 16; o; o >>= 1) {
        sr  += __shfl_xor_sync(0xffffffffu, sr,  o);
        si  += __shfl_xor_sync(0xffffffffu, si,  o);
        srr += __shfl_xor_sync(0xffffffffu, srr, o);
        sii += __shfl_xor_sync(0xffffffffu, sii, o);
        sri += __shfl_xor_sync(0xffffffffu, sri, o);
    }
    if ((tid & 31) == 0) {
        const int w = tid >> 5;
        red[0][w] = sr; red[1][w] = si; red[2][w] = srr;
        red[3][w] = sii; red[4][w] = sri;
    }
    __syncthreads();
    float Sr = 0, Si = 0, Srr = 0, Sii = 0, Sri = 0;
    #pragma unroll
    for (int i = 0; i < 8; i++) {
        Sr += red[0][i]; Si += red[1][i]; Srr += red[2][i];
        Sii += red[3][i]; Sri += red[4][i];
    }
    const float invD = 1.0f / 1024.0f;
    const float mr = Sr * invD, mi = Si * invD;
    const float vr = (Srr * invD - mr * mr) - (Sii * invD - mi * mi) + 1e-6f;
    const float vi = 2.0f * (Sri * invD - mr * mi);
    const float rad = sqrtf(vr * vr + vi * vi);
    const float c  = sqrtf(fmaxf(0.5f * (rad + vr), 0.0f));
    const float dd = copysignf(sqrtf(fmaxf(0.5f * (rad - vr), 0.0f)), vi);
    const float inv = 1.0f / (c * c + dd * dd);

    const int d0 = tid * 4;
    const float4 A2 = ((const float4*)a2)[tid];
    const float4 B2 = ((const float4*)b2)[tid];
    float4 yr, yi;
    { float wr = ar.x - mr, wi = ai.x - mi;
      yr.x = (wr*c + wi*dd)*inv*A2.x + B2.x; yi.x = (wi*c - wr*dd)*inv*A2.x; }
    { float wr = ar.y - mr, wi = ai.y - mi;
      yr.y = (wr*c + wi*dd)*inv*A2.y + B2.y; yi.y = (wi*c - wr*dd)*inv*A2.y; }
    { float wr = ar.z - mr, wi = ai.z - mi;
      yr.z = (wr*c + wi*dd)*inv*A2.z + B2.z; yi.z = (wi*c - wr*dd)*inv*A2.z; }
    { float wr = ar.w - mr, wi = ai.w - mi;
      yr.w = (wr*c + wi*dd)*inv*A2.w + B2.w; yi.w = (wi*c - wr*dd)*inv*A2.w; }
    *(float4*)&out[row * 1024 + d0] = yr;
    *(float4*)&out[(size_t)PLANE + row * 1024 + d0] = yi;
}

// ---------------------------------------------------------------------------
extern "C" void kernel_launch(void* const* d_in, const int* in_sizes, int n_in,
                              void* d_out, int out_size) {
    (void)in_sizes; (void)n_in; (void)out_size;
    cudaFuncSetAttribute(gemm_k<0>, cudaFuncAttributeMaxDynamicSharedMemorySize, DSM_BYTES);
    cudaFuncSetAttribute(gemm_k<1>, cudaFuncAttributeMaxDynamicSharedMemorySize, DSM_BYTES);

    // split inputs + weights into bf16 hi/lo
    for (int j = 0; j < 6; j++)
        split_k<<<PLANE / 4 / 256, 256>>>(j, (const float4*)d_in[j]);
    for (int j = 0; j < 6; j++)
        split_k<<<(DD_ * DD_) / 4 / 256, 256>>>(6 + j, (const float4*)d_in[6 + 2 * j]);

    // 6 projections (X @ W^T + b) -> split bf16
    for (int j = 0; j < 6; j++)
        gemm_k<1><<<dim3(4, 128, 1), 256, DSM_BYTES>>>(j, (const float*)d_in[7 + 2 * j]);

    // transpose kr, vr, vi (hi+lo) per batch
    transpose_k<<<dim3(32, 32, 48), dim3(32, 8)>>>();

    // scores = qr@krT + qi@ki^T  (fp32)
    gemm_k<0><<<dim3(4, 8, 16), 256, DSM_BYTES>>>(6, nullptr);

    // softmax (+0.125 scale) -> split bf16 attn
    softmax_k<<<MTOT, 256>>>();

    // out_r = attn@vr, out_i = attn@vi
    gemm_k<0><<<dim3(4, 8, 16), 256, DSM_BYTES>>>(7, nullptr);
    gemm_k<0><<<dim3(4, 8, 16), 256, DSM_BYTES>>>(8, nullptr);

    // complex LayerNorm -> [2,B,S,D]
    lnorm_k<<<MTOT, 256>>>((const float*)d_in[18], (const float*)d_in[19], (float*)d_out);
}

// round 5
// speedup vs baseline: 1.1501x; 1.1501x over previous
#include <cuda_runtime.h>
#include <cuda_bf16.h>
#include <cstdint>

typedef __nv_bfloat16 bf;

#define NB 16
#define SS_ 1024
#define DD_ 1024
#define MTOT (NB*SS_)              // 16384
#define PLANE (MTOT*DD_)           // 16,777,216
#define BATSTR (SS_*DD_)           // 1,048,576

// ---------------- device scratch (statics; no allocation allowed) ----------
__device__ bf g_xh[6][PLANE];      __device__ bf g_xl[6][PLANE];      // split inputs
__device__ bf g_wh[6][DD_*DD_];    __device__ bf g_wl[6][DD_*DD_];    // split weights
__device__ bf g_ph[6][PLANE];      __device__ bf g_pl[6][PLANE];      // proj outputs
__device__ bf g_th[3][PLANE];      __device__ bf g_tl[3][PLANE];      // transposed kr,vr,vi
__device__ bf g_ah[PLANE];         __device__ bf g_al[PLANE];         // split attn
__device__ float g_att[PLANE];     // raw scores
__device__ float g_or[PLANE];      __device__ float g_oi[PLANE];

// ---------------- helpers ---------------------------------------------------
__device__ __forceinline__ uint32_t smem_u32(const void* p) {
    uint32_t a;
    asm("{ .reg .u64 t; cvta.to.shared.u64 t, %1; cvt.u32.u64 %0, t; }"
        : "=r"(a) : "l"(p));
    return a;
}
__device__ __forceinline__ void cp16(uint32_t s, const void* g) {
    asm volatile("cp.async.cg.shared.global [%0], [%1], 16;" :: "r"(s), "l"(g));
}
#define CP_COMMIT() asm volatile("cp.async.commit_group;" ::: "memory")
#define CP_WAIT2()  asm volatile("cp.async.wait_group 2;" ::: "memory")
#define CP_WAIT0()  asm volatile("cp.async.wait_group 0;" ::: "memory")

__device__ __forceinline__ void ldm4(uint32_t* r, uint32_t addr) {
    asm volatile("ldmatrix.sync.aligned.m8n8.x4.shared.b16 {%0,%1,%2,%3}, [%4];"
        : "=r"(r[0]), "=r"(r[1]), "=r"(r[2]), "=r"(r[3]) : "r"(addr));
}
__device__ __forceinline__ void mma16816(float* d, const uint32_t* a, const uint32_t* b) {
    asm volatile(
        "mma.sync.aligned.m16n8k16.row.col.f32.bf16.bf16.f32 "
        "{%0,%1,%2,%3}, {%4,%5,%6,%7}, {%8,%9}, {%0,%1,%2,%3};"
        : "+f"(d[0]), "+f"(d[1]), "+f"(d[2]), "+f"(d[3])
        : "r"(a[0]), "r"(a[1]), "r"(a[2]), "r"(a[3]), "r"(b[0]), "r"(b[1]));
}

// ---------------- tensor-core split-bf16 NT GEMM ----------------------------
// C[m,n] = sum_pair sum_k A[m,k]*B[n,k], fp32 acc, 3-part bf16 split:
//   hi*hi + hi*lo + lo*hi  (error ~2^-16)
#define BM 128
#define BN 128
#define STAGES 4
#define PITCHB 80                   // 32 bf16 + 8 pad  -> 80 bytes/row
#define PART_BYTES (128*PITCHB)     // 10240
#define STG_BYTES (4*PART_BYTES)    // 40960 (Ah, Al, Bh, Bl)
#define DSM_BYTES (STAGES*STG_BYTES)

// EPI: 0 = write fp32 C ; 1 = add bias, write split bf16 hi/lo
template<int EPI>
__global__ __launch_bounds__(256, 1) void gemm_k(int job, const float* __restrict__ bias) {
    const bf *Ah[2], *Al[2], *Bh[2], *Bl[2];
    size_t bstr = 0; int npair = 1;
    float* Cf = nullptr; bf* Ch = nullptr; bf* Cl = nullptr;
    if (job < 6) {            // projections: X @ W^T + b -> split bf16
        Ah[0] = g_xh[job]; Al[0] = g_xl[job];
        Bh[0] = g_wh[job]; Bl[0] = g_wl[job];
        Ch = g_ph[job]; Cl = g_pl[job];
        Ah[1] = Ah[0]; Al[1] = Al[0]; Bh[1] = Bh[0]; Bl[1] = Bl[0];
    } else if (job == 6) {    // scores: qr@krT + qi@ki^T
        Ah[0] = g_ph[0]; Al[0] = g_pl[0]; Bh[0] = g_th[0]; Bl[0] = g_tl[0];
        Ah[1] = g_ph[1]; Al[1] = g_pl[1]; Bh[1] = g_ph[3]; Bl[1] = g_pl[3];
        npair = 2; bstr = BATSTR; Cf = g_att;
    } else {                  // av: attn @ v
        int w = job - 7;
        Ah[0] = g_ah; Al[0] = g_al;
        Bh[0] = g_th[1 + w]; Bl[0] = g_tl[1 + w];
        bstr = BATSTR; Cf = w ? g_oi : g_or;
        Ah[1] = Ah[0]; Al[1] = Al[0]; Bh[1] = Bh[0]; Bl[1] = Bl[0];
    }
    const size_t zoff  = (size_t)blockIdx.z * bstr;     // element offset
    const size_t zoffb = zoff * 2;                      // byte offset
    const int m0 = blockIdx.y * BM, n0 = blockIdx.x * BN;
    const int T = npair * 32;                           // k-tiles of 32

    extern __shared__ char dsm[];
    const uint32_t base = smem_u32(dsm);
    const int tid = threadIdx.x, wid = tid >> 5, lane = tid & 31;
    const int wm = (wid >> 2) * 64;                     // warp m-offset
    const int wn = (wid & 3) * 32;                      // warp n-offset

    // cp.async mapping: each thread owns 2 consecutive 16B chunks per part
    const int ld_row = tid >> 1;            // 0..127
    const int ld_col = (tid & 1) * 2;       // chunk 0/2

    auto loads = [&](int it, int s) {
        const int pr = it >> 5;             // pair (scores only)
        const int kt = it & 31;             // k-tile within 1024
        const uint32_t sb = base + s * STG_BYTES;
        const size_t ga = zoffb + ((size_t)(m0 + ld_row) * 1024 + kt * 32) * 2 + ld_col * 16;
        const size_t gb = zoffb + ((size_t)(n0 + ld_row) * 1024 + kt * 32) * 2 + ld_col * 16;
        const uint32_t so = ld_row * PITCHB + ld_col * 16;
        const char* pAh = (const char*)Ah[pr] + ga;
        const char* pAl = (const char*)Al[pr] + ga;
        const char* pBh = (const char*)Bh[pr] + gb;
        const char* pBl = (const char*)Bl[pr] + gb;
        cp16(sb + so,                    pAh);
        cp16(sb + so + 16,               pAh + 16);
        cp16(sb + PART_BYTES + so,       pAl);
        cp16(sb + PART_BYTES + so + 16,  pAl + 16);
        cp16(sb + 2*PART_BYTES + so,     pBh);
        cp16(sb + 2*PART_BYTES + so + 16, pBh + 16);
        cp16(sb + 3*PART_BYTES + so,     pBl);
        cp16(sb + 3*PART_BYTES + so + 16, pBl + 16);
    };

    // ldmatrix per-lane address components
    const int g = lane >> 3, lr = lane & 7;
    const uint32_t a_row = ((g & 1) * 8 + lr) * PITCHB;
    const uint32_t a_col = (g >> 1) * 16;
    const uint32_t b_row = ((g >> 1) * 8 + lr) * PITCHB;
    const uint32_t b_col = (g & 1) * 16;

    float acc[4][4][4] = {};

    for (int s = 0; s < STAGES - 1; ++s) {
        if (s < T) loads(s, s);
        CP_COMMIT();
    }

    for (int it = 0; it < T; ++it) {
        CP_WAIT2();
        __syncthreads();
        if (it + STAGES - 1 < T) loads(it + STAGES - 1, (it + STAGES - 1) % STAGES);
        CP_COMMIT();

        const uint32_t sb = base + (it % STAGES) * STG_BYTES;
        #pragma unroll
        for (int ks = 0; ks < 2; ++ks) {
            uint32_t ah[4][4], al[4][4], bh4[2][4], bl4[2][4];
            const uint32_t ak = ks * 32 + a_col;
            const uint32_t bk = ks * 32 + b_col;
            #pragma unroll
            for (int mf = 0; mf < 4; ++mf) {
                const uint32_t ro = (uint32_t)(wm + mf * 16) * PITCHB + a_row + ak;
                ldm4(ah[mf], sb + ro);
                ldm4(al[mf], sb + PART_BYTES + ro);
            }
            #pragma unroll
            for (int nf2 = 0; nf2 < 2; ++nf2) {
                const uint32_t ro = (uint32_t)(wn + nf2 * 16) * PITCHB + b_row + bk;
                ldm4(bh4[nf2], sb + 2*PART_BYTES + ro);
                ldm4(bl4[nf2], sb + 3*PART_BYTES + ro);
            }
            #pragma unroll
            for (int mi = 0; mi < 4; ++mi)
                #pragma unroll
                for (int ni = 0; ni < 4; ++ni) {
                    const uint32_t* bh_f = &bh4[ni >> 1][(ni & 1) * 2];
                    const uint32_t* bl_f = &bl4[ni >> 1][(ni & 1) * 2];
                    mma16816(acc[mi][ni], ah[mi], bh_f);   // hi*hi
                    mma16816(acc[mi][ni], ah[mi], bl_f);   // hi*lo
                    mma16816(acc[mi][ni], al[mi], bh_f);   // lo*hi
                }
        }
    }
    CP_WAIT0();

    // ---------------- epilogue (register -> gmem) ----------------
    const int em = m0 + wm + (lane >> 2);
    const int en = n0 + wn + (lane & 3) * 2;
    #pragma unroll
    for (int mi = 0; mi < 4; ++mi) {
        #pragma unroll
        for (int ni = 0; ni < 4; ++ni) {
            const int m = em + mi * 16;
            const int n = en + ni * 8;
            const float* a = acc[mi][ni];
            if (EPI == 0) {
                float2 v0 = {a[0], a[1]};
                float2 v1 = {a[2], a[3]};
                *(float2*)&Cf[zoff + (size_t)m * 1024 + n]       = v0;
                *(float2*)&Cf[zoff + (size_t)(m + 8) * 1024 + n] = v1;
            } else {
                const float b0 = __ldg(&bias[n]), b1 = __ldg(&bias[n + 1]);
                #pragma unroll
                for (int rr = 0; rr < 2; ++rr) {
                    const float v0 = a[rr * 2 + 0] + b0;
                    const float v1 = a[rr * 2 + 1] + b1;
                    bf h0 = __float2bfloat16_rn(v0), h1 = __float2bfloat16_rn(v1);
                    bf l0 = __float2bfloat16_rn(v0 - __bfloat162float(h0));
                    bf l1 = __float2bfloat16_rn(v1 - __bfloat162float(h1));
                    const size_t off = (size_t)(m + rr * 8) * 1024 + n;
                    __nv_bfloat162 t;
                    t.x = h0; t.y = h1; *(__nv_bfloat162*)(Ch + off) = t;
                    t.x = l0; t.y = l1; *(__nv_bfloat162*)(Cl + off) = t;
                }
            }
        }
    }
}

// ---------------- fp32 -> (hi, lo) bf16 split (merged, grid.y = tensor) -----
struct SplitArgs { const float4* src[6]; };

// MODE 0: weights (1M elems each) -> g_wh/g_wl ; MODE 1: inputs (16M) -> g_xh/g_xl
template<int MODE>
__global__ __launch_bounds__(256) void split6_k(SplitArgs sa) {
    const int job = blockIdx.y;
    bf* h = (MODE == 0) ? g_wh[job] : g_xh[job];
    bf* l = (MODE == 0) ? g_wl[job] : g_xl[job];
    const float4* src = sa.src[job];
    const int i = blockIdx.x * 256 + threadIdx.x;
    const float4 v = src[i];
    bf h0 = __float2bfloat16_rn(v.x), h1 = __float2bfloat16_rn(v.y);
    bf h2 = __float2bfloat16_rn(v.z), h3 = __float2bfloat16_rn(v.w);
    bf l0 = __float2bfloat16_rn(v.x - __bfloat162float(h0));
    bf l1 = __float2bfloat16_rn(v.y - __bfloat162float(h1));
    bf l2 = __float2bfloat16_rn(v.z - __bfloat162float(h2));
    bf l3 = __float2bfloat16_rn(v.w - __bfloat162float(h3));
    __nv_bfloat162 t;
    t.x = h0; t.y = h1; *(__nv_bfloat162*)(h + 4 * (size_t)i)     = t;
    t.x = h2; t.y = h3; *(__nv_bfloat162*)(h + 4 * (size_t)i + 2) = t;
    t.x = l0; t.y = l1; *(__nv_bfloat162*)(l + 4 * (size_t)i)     = t;
    t.x = l2; t.y = l3; *(__nv_bfloat162*)(l + 4 * (size_t)i + 2) = t;
}

// ---------------- batched 1024x1024 bf16 transpose (kr, vr, vi hi+lo) -------
__global__ __launch_bounds__(256) void transpose_k() {
    const int z = blockIdx.z, t = z >> 4, b = z & 15;
    const int si = (t == 0) ? 2 : (t == 1 ? 4 : 5);
    const bf* sh = g_ph[si] + (size_t)b * BATSTR;
    const bf* sl = g_pl[si] + (size_t)b * BATSTR;
    bf* dh = g_th[t] + (size_t)b * BATSTR;
    bf* dl = g_tl[t] + (size_t)b * BATSTR;
    __shared__ bf Th[32][33], Tl[32][33];
    const int tx = threadIdx.x, ty = threadIdx.y;
    const int x0 = blockIdx.x * 32, y0 = blockIdx.y * 32;
    #pragma unroll
    for (int j = ty; j < 32; j += 8) {
        Th[j][tx] = sh[(size_t)(y0 + j) * 1024 + x0 + tx];
        Tl[j][tx] = sl[(size_t)(y0 + j) * 1024 + x0 + tx];
    }
    __syncthreads();
    #pragma unroll
    for (int j = ty; j < 32; j += 8) {
        dh[(size_t)(x0 + j) * 1024 + y0 + tx] = Th[tx][j];
        dl[(size_t)(x0 + j) * 1024 + y0 + tx] = Tl[tx][j];
    }
}

// ---------------- softmax (scale 0.125 folded) -> split bf16 -----------------
__global__ __launch_bounds__(256) void softmax_k() {
    __shared__ float red[8];
    const size_t rowo = (size_t)blockIdx.x * 1024;
    const float* p = g_att + rowo;
    const int tid = threadIdx.x;

    float4 v = ((const float4*)p)[tid];
    v.x *= 0.125f; v.y *= 0.125f; v.z *= 0.125f; v.w *= 0.125f;

    float m = fmaxf(fmaxf(v.x, v.y), fmaxf(v.z, v.w));
    #pragma unroll
    for (int o = 16; o; o >>= 1) m = fmaxf(m, __shfl_xor_sync(0xffffffffu, m, o));
    if ((tid & 31) == 0) red[tid >> 5] = m;
    __syncthreads();
    float M = red[0];
    #pragma unroll
    for (int i = 1; i < 8; i++) M = fmaxf(M, red[i]);
    __syncthreads();

    v.x = expf(v.x - M); v.y = expf(v.y - M);
    v.z = expf(v.z - M); v.w = expf(v.w - M);
    float s = v.x + v.y + v.z + v.w;
    #pragma unroll
    for (int o = 16; o; o >>= 1) s += __shfl_xor_sync(0xffffffffu, s, o);
    if ((tid & 31) == 0) red[tid >> 5] = s;
    __syncthreads();
    float Tt = 0.f;
    #pragma unroll
    for (int i = 0; i < 8; i++) Tt += red[i];
    const float inv = 1.0f / Tt;
    v.x *= inv; v.y *= inv; v.z *= inv; v.w *= inv;

    bf h0 = __float2bfloat16_rn(v.x), h1 = __float2bfloat16_rn(v.y);
    bf h2 = __float2bfloat16_rn(v.z), h3 = __float2bfloat16_rn(v.w);
    bf l0 = __float2bfloat16_rn(v.x - __bfloat162float(h0));
    bf l1 = __float2bfloat16_rn(v.y - __bfloat162float(h1));
    bf l2 = __float2bfloat16_rn(v.z - __bfloat162float(h2));
    bf l3 = __float2bfloat16_rn(v.w - __bfloat162float(h3));
    const size_t o4 = rowo + (size_t)tid * 4;
    __nv_bfloat162 t;
    t.x = h0; t.y = h1; *(__nv_bfloat162*)(g_ah + o4)     = t;
    t.x = h2; t.y = h3; *(__nv_bfloat162*)(g_ah + o4 + 2) = t;
    t.x = l0; t.y = l1; *(__nv_bfloat162*)(g_al + o4)     = t;
    t.x = l2; t.y = l3; *(__nv_bfloat162*)(g_al + o4 + 2) = t;
}

// ---------------- complex LayerNorm + writeback ------------------------------
__global__ __launch_bounds__(256) void lnorm_k(const float* __restrict__ a2,
                                               const float* __restrict__ b2,
                                               float* __restrict__ out) {
    __shared__ float red[5][8];
    const size_t row = blockIdx.x;
    const int tid = threadIdx.x;
    const float4 ar = ((const float4*)(g_or + row * 1024))[tid];
    const float4 ai = ((const float4*)(g_oi + row * 1024))[tid];

    float sr  = ar.x + ar.y + ar.z + ar.w;
    float si  = ai.x + ai.y + ai.z + ai.w;
    float srr = ar.x*ar.x + ar.y*ar.y + ar.z*ar.z + ar.w*ar.w;
    float sii = ai.x*ai.x + ai.y*ai.y + ai.z*ai.z + ai.w*ai.w;
    float sri = ar.x*ai.x + ar.y*ai.y + ar.z*ai.z + ar.w*ai.w;
    #pragma unroll
    for (int o = 16; o; o >>= 1) {
        sr  += __shfl_xor_sync(0xffffffffu, sr,  o);
        si  += __shfl_xor_sync(0xffffffffu, si,  o);
        srr += __shfl_xor_sync(0xffffffffu, srr, o);
        sii += __shfl_xor_sync(0xffffffffu, sii, o);
        sri += __shfl_xor_sync(0xffffffffu, sri, o);
    }
    if ((tid & 31) == 0) {
        const int w = tid >> 5;
        red[0][w] = sr; red[1][w] = si; red[2][w] = srr;
        red[3][w] = sii; red[4][w] = sri;
    }
    __syncthreads();
    float Sr = 0, Si = 0, Srr = 0, Sii = 0, Sri = 0;
    #pragma unroll
    for (int i = 0; i < 8; i++) {
        Sr += red[0][i]; Si += red[1][i]; Srr += red[2][i];
        Sii += red[3][i]; Sri += red[4][i];
    }
    const float invD = 1.0f / 1024.0f;
    const float mr = Sr * invD, mi = Si * invD;
    const float vr = (Srr * invD - mr * mr) - (Sii * invD - mi * mi) + 1e-6f;
    const float vi = 2.0f * (Sri * invD - mr * mi);
    const float rad = sqrtf(vr * vr + vi * vi);
    const float c  = sqrtf(fmaxf(0.5f * (rad + vr), 0.0f));
    const float dd = copysignf(sqrtf(fmaxf(0.5f * (rad - vr), 0.0f)), vi);
    const float inv = 1.0f / (c * c + dd * dd);

    const int d0 = tid * 4;
    const float4 A2 = ((const float4*)a2)[tid];
    const float4 B2 = ((const float4*)b2)[tid];
    float4 yr, yi;
    { float wr = ar.x - mr, wi = ai.x - mi;
      yr.x = (wr*c + wi*dd)*inv*A2.x + B2.x; yi.x = (wi*c - wr*dd)*inv*A2.x; }
    { float wr = ar.y - mr, wi = ai.y - mi;
      yr.y = (wr*c + wi*dd)*inv*A2.y + B2.y; yi.y = (wi*c - wr*dd)*inv*A2.y; }
    { float wr = ar.z - mr, wi = ai.z - mi;
      yr.z = (wr*c + wi*dd)*inv*A2.z + B2.z; yi.z = (wi*c - wr*dd)*inv*A2.z; }
    { float wr = ar.w - mr, wi = ai.w - mi;
      yr.w = (wr*c + wi*dd)*inv*A2.w + B2.w; yi.w = (wi*c - wr*dd)*inv*A2.w; }
    *(float4*)&out[row * 1024 + d0] = yr;
    *(float4*)&out[(size_t)PLANE + row * 1024 + d0] = yi;
}

// ---------------------------------------------------------------------------
extern "C" void kernel_launch(void* const* d_in, const int* in_sizes, int n_in,
                              void* d_out, int out_size) {
    (void)in_sizes; (void)n_in; (void)out_size;
    cudaFuncSetAttribute(gemm_k<0>, cudaFuncAttributeMaxDynamicSharedMemorySize, DSM_BYTES);
    cudaFuncSetAttribute(gemm_k<1>, cudaFuncAttributeMaxDynamicSharedMemorySize, DSM_BYTES);

    // launch order note: ncu capture is (-s 5 -c 1) -> profiles launch #6,
    // which with this ordering is proj GEMM job=3.
    SplitArgs sw, sx;
    for (int j = 0; j < 6; j++) {
        sx.src[j] = (const float4*)d_in[j];
        sw.src[j] = (const float4*)d_in[6 + 2 * j];
    }
    // 1: weights split (6 tensors)
    split6_k<0><<<dim3((DD_ * DD_) / 4 / 256, 6), 256>>>(sw);
    // 2: inputs split (6 tensors)
    split6_k<1><<<dim3(PLANE / 4 / 256, 6), 256>>>(sx);

    // 3..8: projections (X @ W^T + b) -> split bf16
    for (int j = 0; j < 6; j++)
        gemm_k<1><<<dim3(8, 128, 1), 256, DSM_BYTES>>>(j, (const float*)d_in[7 + 2 * j]);

    // 9: transpose kr, vr, vi (hi+lo) per batch
    transpose_k<<<dim3(32, 32, 48), dim3(32, 8)>>>();

    // 10: scores = qr@krT + qi@ki^T  (fp32)
    gemm_k<0><<<dim3(8, 8, 16), 256, DSM_BYTES>>>(6, nullptr);

    // 11: softmax (+0.125 scale) -> split bf16 attn
    softmax_k<<<MTOT, 256>>>();

    // 12, 13: out_r = attn@vr, out_i = attn@vi
    gemm_k<0><<<dim3(8, 8, 16), 256, DSM_BYTES>>>(7, nullptr);
    gemm_k<0><<<dim3(8, 8, 16), 256, DSM_BYTES>>>(8, nullptr);

    // 14: complex LayerNorm -> [2,B,S,D]
    lnorm_k<<<MTOT, 256>>>((const float*)d_in[18], (const float*)d_in[19], (float*)d_out);
}

// round 6
// speedup vs baseline: 1.3296x; 1.1561x over previous
#include <cuda_runtime.h>
#include <cuda_bf16.h>
#include <cstdint>

typedef __nv_bfloat16 bf;

#define NB 16
#define SS_ 1024
#define DD_ 1024
#define MTOT (NB*SS_)              // 16384
#define PLANE (MTOT*DD_)           // 16,777,216
#define BATSTR (SS_*DD_)           // 1,048,576

// ---------------- device scratch (statics; no allocation allowed) ----------
__device__ bf g_xh[6][PLANE];      __device__ bf g_xl[6][PLANE];      // split inputs
__device__ bf g_wh[6][DD_*DD_];    __device__ bf g_wl[6][DD_*DD_];    // split weights
__device__ bf g_ph[6][PLANE];      __device__ bf g_pl[6][PLANE];      // proj outputs
__device__ bf g_th[3][PLANE];      __device__ bf g_tl[3][PLANE];      // transposed kr,vr,vi
__device__ bf g_ah[PLANE];         __device__ bf g_al[PLANE];         // split attn
__device__ float g_att[PLANE];     // raw scores
__device__ float g_or[PLANE];      __device__ float g_oi[PLANE];

// ---------------- helpers ---------------------------------------------------
__device__ __forceinline__ uint32_t smem_u32(const void* p) {
    uint32_t a;
    asm("{ .reg .u64 t; cvta.to.shared.u64 t, %1; cvt.u32.u64 %0, t; }"
        : "=r"(a) : "l"(p));
    return a;
}
__device__ __forceinline__ void cp16(uint32_t s, const void* g) {
    asm volatile("cp.async.cg.shared.global [%0], [%1], 16;" :: "r"(s), "l"(g));
}
#define CP_COMMIT() asm volatile("cp.async.commit_group;" ::: "memory")
#define CP_WAIT1()  asm volatile("cp.async.wait_group 1;" ::: "memory")
#define CP_WAIT0()  asm volatile("cp.async.wait_group 0;" ::: "memory")

__device__ __forceinline__ void ldm4(uint32_t* r, uint32_t addr) {
    asm volatile("ldmatrix.sync.aligned.m8n8.x4.shared.b16 {%0,%1,%2,%3}, [%4];"
        : "=r"(r[0]), "=r"(r[1]), "=r"(r[2]), "=r"(r[3]) : "r"(addr));
}
__device__ __forceinline__ void mma16816(float* d, const uint32_t* a, const uint32_t* b) {
    asm volatile(
        "mma.sync.aligned.m16n8k16.row.col.f32.bf16.bf16.f32 "
        "{%0,%1,%2,%3}, {%4,%5,%6,%7}, {%8,%9}, {%0,%1,%2,%3};"
        : "+f"(d[0]), "+f"(d[1]), "+f"(d[2]), "+f"(d[3])
        : "r"(a[0]), "r"(a[1]), "r"(a[2]), "r"(a[3]), "r"(b[0]), "r"(b[1]));
}

// ---------------- tensor-core split-bf16 NT GEMM ----------------------------
// C[m,n] = sum_pair sum_k A[m,k]*B[n,k], fp32 acc, 3-part bf16 split:
//   hi*hi + hi*lo + lo*hi  (error ~2^-16)
// BM=128, BN=128, BK=32; 8 warps (2x4), warp tile 64x32. 2 CTAs/SM.
#define BM 128
#define BN 128
#define STAGES 2
#define PITCHB 80                   // 32 bf16 + 8 pad  -> 80 bytes/row
#define PART_BYTES (128*PITCHB)     // 10240
#define STG_BYTES (4*PART_BYTES)    // 40960 (Ah, Al, Bh, Bl)
#define DSM_BYTES (STAGES*STG_BYTES) // 81920

struct BiasArr { const float* b[6]; };

// MODE 0: proj (z=job, bf split out, +bias), 1: scores (z=batch), 2: av (z=b|w<<4)
template<int MODE>
__global__ __launch_bounds__(256, 2) void gemm_k(BiasArr ba) {
    const bf *Ah[2], *Al[2], *Bh[2], *Bl[2];
    float* Cf = nullptr; bf* Ch = nullptr; bf* Cl = nullptr;
    const float* bias = nullptr;
    size_t zoff = 0; int T = 32;
    if (MODE == 0) {
        const int job = blockIdx.z;
        Ah[0] = g_xh[job]; Al[0] = g_xl[job];
        Bh[0] = g_wh[job]; Bl[0] = g_wl[job];
        Ch = g_ph[job]; Cl = g_pl[job]; bias = ba.b[job];
        Ah[1] = Ah[0]; Al[1] = Al[0]; Bh[1] = Bh[0]; Bl[1] = Bl[0];
    } else if (MODE == 1) {
        zoff = (size_t)blockIdx.z * BATSTR;
        Ah[0] = g_ph[0]; Al[0] = g_pl[0]; Bh[0] = g_th[0]; Bl[0] = g_tl[0];
        Ah[1] = g_ph[1]; Al[1] = g_pl[1]; Bh[1] = g_ph[3]; Bl[1] = g_pl[3];
        Cf = g_att; T = 64;
    } else {
        const int b = blockIdx.z & 15, w = blockIdx.z >> 4;
        zoff = (size_t)b * BATSTR;
        Ah[0] = g_ah; Al[0] = g_al;
        Bh[0] = g_th[1 + w]; Bl[0] = g_tl[1 + w];
        Cf = w ? g_oi : g_or;
        Ah[1] = Ah[0]; Al[1] = Al[0]; Bh[1] = Bh[0]; Bl[1] = Bl[0];
    }
    const size_t zoffb = zoff * 2;                      // byte offset
    const int m0 = blockIdx.y * BM, n0 = blockIdx.x * BN;

    extern __shared__ char dsm[];
    const uint32_t base = smem_u32(dsm);
    const int tid = threadIdx.x, wid = tid >> 5, lane = tid & 31;
    const int wm = (wid >> 2) * 64;                     // warp m-offset
    const int wn = (wid & 3) * 32;                      // warp n-offset

    // cp.async mapping: each thread owns 2 consecutive 16B chunks per part
    const int ld_row = tid >> 1;            // 0..127
    const int ld_col = (tid & 1) * 2;       // chunk 0/2

    auto loads = [&](int it, int s) {
        const int pr = it >> 5;             // pair (scores only)
        const int kt = it & 31;             // k-tile within 1024
        const uint32_t sb = base + s * STG_BYTES;
        const size_t ga = zoffb + ((size_t)(m0 + ld_row) * 1024 + kt * 32) * 2 + ld_col * 16;
        const size_t gb = zoffb + ((size_t)(n0 + ld_row) * 1024 + kt * 32) * 2 + ld_col * 16;
        const uint32_t so = ld_row * PITCHB + ld_col * 16;
        const char* pAh = (const char*)Ah[pr] + ga;
        const char* pAl = (const char*)Al[pr] + ga;
        const char* pBh = (const char*)Bh[pr] + gb;
        const char* pBl = (const char*)Bl[pr] + gb;
        cp16(sb + so,                     pAh);
        cp16(sb + so + 16,                pAh + 16);
        cp16(sb + PART_BYTES + so,        pAl);
        cp16(sb + PART_BYTES + so + 16,   pAl + 16);
        cp16(sb + 2*PART_BYTES + so,      pBh);
        cp16(sb + 2*PART_BYTES + so + 16, pBh + 16);
        cp16(sb + 3*PART_BYTES + so,      pBl);
        cp16(sb + 3*PART_BYTES + so + 16, pBl + 16);
    };

    // ldmatrix per-lane address components
    const int g = lane >> 3, lr = lane & 7;
    const uint32_t a_row = ((g & 1) * 8 + lr) * PITCHB;
    const uint32_t a_col = (g >> 1) * 16;
    const uint32_t b_row = ((g >> 1) * 8 + lr) * PITCHB;
    const uint32_t b_col = (g & 1) * 16;

    float acc[4][4][4] = {};

    loads(0, 0); CP_COMMIT();
    if (T > 1) loads(1, 1); CP_COMMIT();

    for (int it = 0; it < T; ++it) {
        CP_WAIT1();
        __syncthreads();

        const uint32_t sb = base + (it & 1) * STG_BYTES;
        #pragma unroll
        for (int ks = 0; ks < 2; ++ks) {
            uint32_t bh4[2][4], bl4[2][4];
            const uint32_t ak = ks * 32 + a_col;
            const uint32_t bk = ks * 32 + b_col;
            #pragma unroll
            for (int nf2 = 0; nf2 < 2; ++nf2) {
                const uint32_t ro = (uint32_t)(wn + nf2 * 16) * PITCHB + b_row + bk;
                ldm4(bh4[nf2], sb + 2*PART_BYTES + ro);
                ldm4(bl4[nf2], sb + 3*PART_BYTES + ro);
            }
            #pragma unroll
            for (int mf = 0; mf < 4; ++mf) {
                uint32_t ah[4], al[4];
                const uint32_t ro = (uint32_t)(wm + mf * 16) * PITCHB + a_row + ak;
                ldm4(ah, sb + ro);
                ldm4(al, sb + PART_BYTES + ro);
                #pragma unroll
                for (int ni = 0; ni < 4; ++ni) {
                    const uint32_t* bh_f = &bh4[ni >> 1][(ni & 1) * 2];
                    const uint32_t* bl_f = &bl4[ni >> 1][(ni & 1) * 2];
                    mma16816(acc[mf][ni], ah, bh_f);   // hi*hi
                    mma16816(acc[mf][ni], ah, bl_f);   // hi*lo
                    mma16816(acc[mf][ni], al, bh_f);   // lo*hi
                }
            }
        }
        __syncthreads();
        if (it + 2 < T) loads(it + 2, it & 1);
        CP_COMMIT();
    }
    CP_WAIT0();

    // ---------------- epilogue (register -> gmem) ----------------
    const int em = m0 + wm + (lane >> 2);
    const int en = n0 + wn + (lane & 3) * 2;
    #pragma unroll
    for (int mi = 0; mi < 4; ++mi) {
        #pragma unroll
        for (int ni = 0; ni < 4; ++ni) {
            const int m = em + mi * 16;
            const int n = en + ni * 8;
            const float* a = acc[mi][ni];
            if (MODE != 0) {
                float2 v0 = {a[0], a[1]};
                float2 v1 = {a[2], a[3]};
                *(float2*)&Cf[zoff + (size_t)m * 1024 + n]       = v0;
                *(float2*)&Cf[zoff + (size_t)(m + 8) * 1024 + n] = v1;
            } else {
                const float b0 = __ldg(&bias[n]), b1 = __ldg(&bias[n + 1]);
                #pragma unroll
                for (int rr = 0; rr < 2; ++rr) {
                    const float v0 = a[rr * 2 + 0] + b0;
                    const float v1 = a[rr * 2 + 1] + b1;
                    bf h0 = __float2bfloat16_rn(v0), h1 = __float2bfloat16_rn(v1);
                    bf l0 = __float2bfloat16_rn(v0 - __bfloat162float(h0));
                    bf l1 = __float2bfloat16_rn(v1 - __bfloat162float(h1));
                    const size_t off = (size_t)(m + rr * 8) * 1024 + n;
                    __nv_bfloat162 t;
                    t.x = h0; t.y = h1; *(__nv_bfloat162*)(Ch + off) = t;
                    t.x = l0; t.y = l1; *(__nv_bfloat162*)(Cl + off) = t;
                }
            }
        }
    }
}

// ---------------- fp32 -> (hi, lo) bf16 split (merged, grid.y = tensor) -----
struct SplitArgs { const float4* src[6]; };

// MODE 0: weights (1M elems each) -> g_wh/g_wl ; MODE 1: inputs (16M) -> g_xh/g_xl
template<int MODE>
__global__ __launch_bounds__(256) void split6_k(SplitArgs sa) {
    const int job = blockIdx.y;
    bf* h = (MODE == 0) ? g_wh[job] : g_xh[job];
    bf* l = (MODE == 0) ? g_wl[job] : g_xl[job];
    const float4* src = sa.src[job];
    const int i = blockIdx.x * 256 + threadIdx.x;
    const float4 v = src[i];
    bf h0 = __float2bfloat16_rn(v.x), h1 = __float2bfloat16_rn(v.y);
    bf h2 = __float2bfloat16_rn(v.z), h3 = __float2bfloat16_rn(v.w);
    bf l0 = __float2bfloat16_rn(v.x - __bfloat162float(h0));
    bf l1 = __float2bfloat16_rn(v.y - __bfloat162float(h1));
    bf l2 = __float2bfloat16_rn(v.z - __bfloat162float(h2));
    bf l3 = __float2bfloat16_rn(v.w - __bfloat162float(h3));
    __nv_bfloat162 t;
    t.x = h0; t.y = h1; *(__nv_bfloat162*)(h + 4 * (size_t)i)     = t;
    t.x = h2; t.y = h3; *(__nv_bfloat162*)(h + 4 * (size_t)i + 2) = t;
    t.x = l0; t.y = l1; *(__nv_bfloat162*)(l + 4 * (size_t)i)     = t;
    t.x = l2; t.y = l3; *(__nv_bfloat162*)(l + 4 * (size_t)i + 2) = t;
}

// ---------------- batched 1024x1024 bf16 transpose (kr, vr, vi hi+lo) -------
__global__ __launch_bounds__(256) void transpose_k(int tbase) {
    const int z = blockIdx.z, t = tbase + (z >> 4), b = z & 15;
    const int si = (t == 0) ? 2 : (t == 1 ? 4 : 5);
    const bf* sh = g_ph[si] + (size_t)b * BATSTR;
    const bf* sl = g_pl[si] + (size_t)b * BATSTR;
    bf* dh = g_th[t] + (size_t)b * BATSTR;
    bf* dl = g_tl[t] + (size_t)b * BATSTR;
    __shared__ bf Th[32][33], Tl[32][33];
    const int tx = threadIdx.x, ty = threadIdx.y;
    const int x0 = blockIdx.x * 32, y0 = blockIdx.y * 32;
    #pragma unroll
    for (int j = ty; j < 32; j += 8) {
        Th[j][tx] = sh[(size_t)(y0 + j) * 1024 + x0 + tx];
        Tl[j][tx] = sl[(size_t)(y0 + j) * 1024 + x0 + tx];
    }
    __syncthreads();
    #pragma unroll
    for (int j = ty; j < 32; j += 8) {
        dh[(size_t)(x0 + j) * 1024 + y0 + tx] = Th[tx][j];
        dl[(size_t)(x0 + j) * 1024 + y0 + tx] = Tl[tx][j];
    }
}

// ---------------- softmax (scale 0.125 folded) -> split bf16 -----------------
__global__ __launch_bounds__(256) void softmax_k() {
    __shared__ float red[8];
    const size_t rowo = (size_t)blockIdx.x * 1024;
    const float* p = g_att + rowo;
    const int tid = threadIdx.x;

    float4 v = ((const float4*)p)[tid];
    v.x *= 0.125f; v.y *= 0.125f; v.z *= 0.125f; v.w *= 0.125f;

    float m = fmaxf(fmaxf(v.x, v.y), fmaxf(v.z, v.w));
    #pragma unroll
    for (int o = 16; o; o >>= 1) m = fmaxf(m, __shfl_xor_sync(0xffffffffu, m, o));
    if ((tid & 31) == 0) red[tid >> 5] = m;
    __syncthreads();
    float M = red[0];
    #pragma unroll
    for (int i = 1; i < 8; i++) M = fmaxf(M, red[i]);
    __syncthreads();

    v.x = expf(v.x - M); v.y = expf(v.y - M);
    v.z = expf(v.z - M); v.w = expf(v.w - M);
    float s = v.x + v.y + v.z + v.w;
    #pragma unroll
    for (int o = 16; o; o >>= 1) s += __shfl_xor_sync(0xffffffffu, s, o);
    if ((tid & 31) == 0) red[tid >> 5] = s;
    __syncthreads();
    float Tt = 0.f;
    #pragma unroll
    for (int i = 0; i < 8; i++) Tt += red[i];
    const float inv = 1.0f / Tt;
    v.x *= inv; v.y *= inv; v.z *= inv; v.w *= inv;

    bf h0 = __float2bfloat16_rn(v.x), h1 = __float2bfloat16_rn(v.y);
    bf h2 = __float2bfloat16_rn(v.z), h3 = __float2bfloat16_rn(v.w);
    bf l0 = __float2bfloat16_rn(v.x - __bfloat162float(h0));
    bf l1 = __float2bfloat16_rn(v.y - __bfloat162float(h1));
    bf l2 = __float2bfloat16_rn(v.z - __bfloat162float(h2));
    bf l3 = __float2bfloat16_rn(v.w - __bfloat162float(h3));
    const size_t o4 = rowo + (size_t)tid * 4;
    __nv_bfloat162 t;
    t.x = h0; t.y = h1; *(__nv_bfloat162*)(g_ah + o4)     = t;
    t.x = h2; t.y = h3; *(__nv_bfloat162*)(g_ah + o4 + 2) = t;
    t.x = l0; t.y = l1; *(__nv_bfloat162*)(g_al + o4)     = t;
    t.x = l2; t.y = l3; *(__nv_bfloat162*)(g_al + o4 + 2) = t;
}

// ---------------- complex LayerNorm + writeback ------------------------------
__global__ __launch_bounds__(256) void lnorm_k(const float* __restrict__ a2,
                                               const float* __restrict__ b2,
                                               float* __restrict__ out) {
    __shared__ float red[5][8];
    const size_t row = blockIdx.x;
    const int tid = threadIdx.x;
    const float4 ar = ((const float4*)(g_or + row * 1024))[tid];
    const float4 ai = ((const float4*)(g_oi + row * 1024))[tid];

    float sr  = ar.x + ar.y + ar.z + ar.w;
    float si  = ai.x + ai.y + ai.z + ai.w;
    float srr = ar.x*ar.x + ar.y*ar.y + ar.z*ar.z + ar.w*ar.w;
    float sii = ai.x*ai.x + ai.y*ai.y + ai.z*ai.z + ai.w*ai.w;
    float sri = ar.x*ai.x + ar.y*ai.y + ar.z*ai.z + ar.w*ai.w;
    #pragma unroll
    for (int o = 16; o; o >>= 1) {
        sr  += __shfl_xor_sync(0xffffffffu, sr,  o);
        si  += __shfl_xor_sync(0xffffffffu, si,  o);
        srr += __shfl_xor_sync(0xffffffffu, srr, o);
        sii += __shfl_xor_sync(0xffffffffu, sii, o);
        sri += __shfl_xor_sync(0xffffffffu, sri, o);
    }
    if ((tid & 31) == 0) {
        const int w = tid >> 5;
        red[0][w] = sr; red[1][w] = si; red[2][w] = srr;
        red[3][w] = sii; red[4][w] = sri;
    }
    __syncthreads();
    float Sr = 0, Si = 0, Srr = 0, Sii = 0, Sri = 0;
    #pragma unroll
    for (int i = 0; i < 8; i++) {
        Sr += red[0][i]; Si += red[1][i]; Srr += red[2][i];
        Sii += red[3][i]; Sri += red[4][i];
    }
    const float invD = 1.0f / 1024.0f;
    const float mr = Sr * invD, mi = Si * invD;
    const float vr = (Srr * invD - mr * mr) - (Sii * invD - mi * mi) + 1e-6f;
    const float vi = 2.0f * (Sri * invD - mr * mi);
    const float rad = sqrtf(vr * vr + vi * vi);
    const float c  = sqrtf(fmaxf(0.5f * (rad + vr), 0.0f));
    const float dd = copysignf(sqrtf(fmaxf(0.5f * (rad - vr), 0.0f)), vi);
    const float inv = 1.0f / (c * c + dd * dd);

    const int d0 = tid * 4;
    const float4 A2 = ((const float4*)a2)[tid];
    const float4 B2 = ((const float4*)b2)[tid];
    float4 yr, yi;
    { float wr = ar.x - mr, wi = ai.x - mi;
      yr.x = (wr*c + wi*dd)*inv*A2.x + B2.x; yi.x = (wi*c - wr*dd)*inv*A2.x; }
    { float wr = ar.y - mr, wi = ai.y - mi;
      yr.y = (wr*c + wi*dd)*inv*A2.y + B2.y; yi.y = (wi*c - wr*dd)*inv*A2.y; }
    { float wr = ar.z - mr, wi = ai.z - mi;
      yr.z = (wr*c + wi*dd)*inv*A2.z + B2.z; yi.z = (wi*c - wr*dd)*inv*A2.z; }
    { float wr = ar.w - mr, wi = ai.w - mi;
      yr.w = (wr*c + wi*dd)*inv*A2.w + B2.w; yi.w = (wi*c - wr*dd)*inv*A2.w; }
    *(float4*)&out[row * 1024 + d0] = yr;
    *(float4*)&out[(size_t)PLANE + row * 1024 + d0] = yi;
}

// ---------------------------------------------------------------------------
extern "C" void kernel_launch(void* const* d_in, const int* in_sizes, int n_in,
                              void* d_out, int out_size) {
    (void)in_sizes; (void)n_in; (void)out_size;
    cudaFuncSetAttribute(gemm_k<0>, cudaFuncAttributeMaxDynamicSharedMemorySize, DSM_BYTES);
    cudaFuncSetAttribute(gemm_k<1>, cudaFuncAttributeMaxDynamicSharedMemorySize, DSM_BYTES);
    cudaFuncSetAttribute(gemm_k<2>, cudaFuncAttributeMaxDynamicSharedMemorySize, DSM_BYTES);

    SplitArgs sw, sx;
    BiasArr ba, bz = {};
    for (int j = 0; j < 6; j++) {
        sx.src[j] = (const float4*)d_in[j];
        sw.src[j] = (const float4*)d_in[6 + 2 * j];
        ba.b[j]   = (const float*)d_in[7 + 2 * j];
    }
    // launch order: ncu (-s 5 -c 1) profiles launch #6 = scores GEMM
    // 1: weights split (6 tensors)
    split6_k<0><<<dim3((DD_ * DD_) / 4 / 256, 6), 256>>>(sw);
    // 2: inputs split (6 tensors)
    split6_k<1><<<dim3(PLANE / 4 / 256, 6), 256>>>(sx);
    // 3: all 6 projections (X @ W^T + b) -> split bf16
    gemm_k<0><<<dim3(8, 128, 6), 256, DSM_BYTES>>>(ba);
    // 4, 5: transpose kr | vr, vi (hi+lo) per batch
    transpose_k<<<dim3(32, 32, 16), dim3(32, 8)>>>(0);
    transpose_k<<<dim3(32, 32, 32), dim3(32, 8)>>>(1);
    // 6: scores = qr@krT + qi@ki^T  (fp32)  <- ncu target
    gemm_k<1><<<dim3(8, 8, 16), 256, DSM_BYTES>>>(bz);
    // 7: softmax (+0.125 scale) -> split bf16 attn
    softmax_k<<<MTOT, 256>>>();
    // 8: out_r = attn@vr AND out_i = attn@vi (merged, grid.z=32)
    gemm_k<2><<<dim3(8, 8, 32), 256, DSM_BYTES>>>(bz);
    // 9: complex LayerNorm -> [2,B,S,D]
    lnorm_k<<<MTOT, 256>>>((const float*)d_in[18], (const float*)d_in[19], (float*)d_out);
}